// round 12
// baseline (speedup 1.0000x reference)
#include <cuda_runtime.h>
#include <cuda_bf16.h>
#include <math.h>
#include <stdint.h>

#define B_ 4
#define N_ 1024
#define HW_ 4096
#define D_ 512
#define H_ 8
#define DK_ 64
#define ZTOT (B_ * H_)
#define DD (D_ * D_)

// ---------------- scratch (static device globals; no allocation) -----------
__device__ __nv_bfloat16 g_qh[B_ * N_ * D_],  g_ql[B_ * N_ * D_];
__device__ __nv_bfloat16 g_kh[B_ * HW_ * D_], g_kl[B_ * HW_ * D_];
__device__ __nv_bfloat16 g_vh[B_ * HW_ * D_], g_vl[B_ * HW_ * D_];
__device__ __nv_bfloat16 g_wh[4 * DD], g_wl[4 * DD];
__device__ __nv_bfloat16 g_Qh[B_ * N_ * D_],  g_Ql[B_ * N_ * D_];
__device__ __nv_bfloat16 g_Kh[B_ * HW_ * D_], g_Kl[B_ * HW_ * D_];
__device__ __nv_bfloat16 g_Vh[B_ * HW_ * D_], g_Vl[B_ * HW_ * D_];
__device__ __nv_bfloat16 g_ctxh[B_ * N_ * D_], g_ctxl[B_ * N_ * D_];
__device__ unsigned long long g_maskb[(size_t)N_ * HW_ / 64];   // bit-packed mask

// ---------------- helpers --------------------------------------------------
__device__ __forceinline__ uint32_t smem_u32(const void* p) {
    return (uint32_t)__cvta_generic_to_shared(p);
}
__device__ __forceinline__ void cp16(uint32_t s, const void* g) {
    asm volatile("cp.async.cg.shared.global [%0],[%1],16;" :: "r"(s), "l"(g));
}
__device__ __forceinline__ void cp_commit() {
    asm volatile("cp.async.commit_group;" ::: "memory");
}
template <int NN>
__device__ __forceinline__ void cp_wait() {
    asm volatile("cp.async.wait_group %0;" :: "n"(NN) : "memory");
}
__device__ __forceinline__ void ldsm4(uint32_t& r0, uint32_t& r1, uint32_t& r2,
                                      uint32_t& r3, uint32_t a) {
    asm volatile("ldmatrix.sync.aligned.m8n8.x4.shared.b16 {%0,%1,%2,%3},[%4];"
                 : "=r"(r0), "=r"(r1), "=r"(r2), "=r"(r3) : "r"(a));
}
__device__ __forceinline__ void ldsm4t(uint32_t& r0, uint32_t& r1, uint32_t& r2,
                                       uint32_t& r3, uint32_t a) {
    asm volatile("ldmatrix.sync.aligned.m8n8.x4.trans.shared.b16 {%0,%1,%2,%3},[%4];"
                 : "=r"(r0), "=r"(r1), "=r"(r2), "=r"(r3) : "r"(a));
}
__device__ __forceinline__ void mma_bf16(float* c, const uint32_t* a, const uint32_t* b) {
    asm volatile(
        "mma.sync.aligned.m16n8k16.row.col.f32.bf16.bf16.f32 "
        "{%0,%1,%2,%3},{%4,%5,%6,%7},{%8,%9},{%0,%1,%2,%3};"
        : "+f"(c[0]), "+f"(c[1]), "+f"(c[2]), "+f"(c[3])
        : "r"(a[0]), "r"(a[1]), "r"(a[2]), "r"(a[3]), "r"(b[0]), "r"(b[1]));
}
__device__ __forceinline__ void mma2(float* c, const uint32_t* a, uint32_t b0, uint32_t b1) {
    uint32_t b[2] = {b0, b1};
    mma_bf16(c, a, b);
}
__device__ __forceinline__ void split2(float x, float y, uint32_t& hi, uint32_t& lo) {
    __nv_bfloat16 hx = __float2bfloat16(x);
    __nv_bfloat16 hy = __float2bfloat16(y);
    __nv_bfloat16 lx = __float2bfloat16(x - __bfloat162float(hx));
    __nv_bfloat16 ly = __float2bfloat16(y - __bfloat162float(hy));
    hi = (uint32_t)__bfloat16_as_ushort(hx) | ((uint32_t)__bfloat16_as_ushort(hy) << 16);
    lo = (uint32_t)__bfloat16_as_ushort(lx) | ((uint32_t)__bfloat16_as_ushort(ly) << 16);
}

// ---------------- single merged split kernel -------------------------------
#define NQ4 (B_ * N_ * D_ / 4)
#define NK4 (B_ * HW_ * D_ / 4)
#define NV4 NK4
#define NW4 DD
#define NTOT4 (NQ4 + NK4 + NV4 + NW4)

__global__ void split_all(const float4* __restrict__ q, const float4* __restrict__ k,
                          const float4* __restrict__ v,
                          const float4* __restrict__ W0, const float4* __restrict__ W1,
                          const float4* __restrict__ W2, const float4* __restrict__ W3,
                          uint2* __restrict__ qh, uint2* __restrict__ ql,
                          uint2* __restrict__ kh, uint2* __restrict__ kl,
                          uint2* __restrict__ vh, uint2* __restrict__ vl,
                          uint2* __restrict__ wh, uint2* __restrict__ wl) {
    int i = blockIdx.x * blockDim.x + threadIdx.x;
    if (i >= NTOT4) return;
    float4 vv;
    uint2 *Hd, *Ld;
    int j;
    if (i < NQ4) { j = i; vv = q[j]; Hd = qh; Ld = ql; }
    else if (i < NQ4 + NK4) { j = i - NQ4; vv = k[j]; Hd = kh; Ld = kl; }
    else if (i < NQ4 + NK4 + NV4) { j = i - NQ4 - NK4; vv = v[j]; Hd = vh; Ld = vl; }
    else {
        j = i - NQ4 - NK4 - NV4;
        int a = j >> 16;
        int r = j & 0xFFFF;
        vv = (a == 0 ? W0 : a == 1 ? W1 : a == 2 ? W2 : W3)[r];
        Hd = wh; Ld = wl;
    }
    uint32_t h0, l0, h1, l1;
    split2(vv.x, vv.y, h0, l0);
    split2(vv.z, vv.w, h1, l1);
    Hd[j] = make_uint2(h0, h1);
    Ld[j] = make_uint2(l0, l1);
}

// ---------------- mask precompute (bit-packed via ballot) ------------------
__global__ void mask_kernel(const float* __restrict__ x_tilde,
                            const float* __restrict__ x_hat,
                            unsigned int* __restrict__ maskb) {
    int idx = blockIdx.x * blockDim.x + threadIdx.x;
    int m = idx & (HW_ - 1);
    float dx = x_tilde[m * 2 + 0] - x_hat[(size_t)idx * 2 + 0];
    float dy = x_tilde[m * 2 + 1] - x_hat[(size_t)idx * 2 + 1];
    unsigned keep = (sqrtf(dx * dx + dy * dy) < 0.1f) ? 1u : 0u;
    unsigned bal = __ballot_sync(0xffffffffu, keep);
    if ((idx & 31) == 0) maskb[idx >> 5] = bal;
}

// ---------------- shared GEMM body (128x128 tile, K=512, split-bf16) -------
#define GBM 128
#define GBN 128
#define GBK 32
#define GSA (GBK + 8)
#define GASZ (GBM * GSA)
#define GBSZ (GBN * GSA)
#define GSTRIDE (2 * GASZ + 2 * GBSZ)
#define SMEM_BIG (3 * GSTRIDE * 2)

template <bool SPLITOUT>
__device__ __forceinline__ void gemm_body(
    __nv_bfloat16* smem,
    const __nv_bfloat16* __restrict__ Agh, const __nv_bfloat16* __restrict__ Agl,
    const __nv_bfloat16* __restrict__ Bgh, const __nv_bfloat16* __restrict__ Bgl,
    const float* __restrict__ bias, float* __restrict__ C,
    __nv_bfloat16* __restrict__ Ch, __nv_bfloat16* __restrict__ Cl,
    int m0, int n0) {
    constexpr int STAGES = 3;
    constexpr int WM = 64, WN = 32;
    constexpr int WNC = GBN / WN;
    constexpr int MT = WM / 16;
    constexpr int NT = WN / 8;
    constexpr int NTP = NT / 2;

    int tid = threadIdx.x;
    int lane = tid & 31;
    int wid = tid >> 5;
    int wm0 = (wid / WNC) * WM;
    int wn0 = (wid % WNC) * WN;

    const int nK = D_ / GBK;
    uint32_t smem_b = smem_u32(smem);

    auto issue = [&](int kc) {
        int s = kc % STAGES;
        int k0 = kc * GBK;
        uint32_t base = smem_b + (uint32_t)(s * GSTRIDE) * 2;
        for (int i = tid; i < GBM * (GBK / 8); i += 256) {
            int r = i / (GBK / 8);
            int c = (i % (GBK / 8)) * 8;
            long go = (long)(m0 + r) * D_ + k0 + c;
            uint32_t so = (uint32_t)(r * GSA + c) * 2;
            cp16(base + so, Agh + go);
            cp16(base + (uint32_t)GASZ * 2 + so, Agl + go);
        }
        uint32_t bb = base + (uint32_t)(2 * GASZ) * 2;
        for (int i = tid; i < GBN * (GBK / 8); i += 256) {
            int r = i / (GBK / 8);
            int c = (i % (GBK / 8)) * 8;
            long go = (long)(n0 + r) * D_ + k0 + c;
            uint32_t so = (uint32_t)(r * GSA + c) * 2;
            cp16(bb + so, Bgh + go);
            cp16(bb + (uint32_t)GBSZ * 2 + so, Bgl + go);
        }
    };

    float acc[MT][NT][4];
#pragma unroll
    for (int i = 0; i < MT; i++)
#pragma unroll
        for (int j = 0; j < NT; j++)
#pragma unroll
            for (int q = 0; q < 4; q++) acc[i][j][q] = 0.0f;

    for (int s = 0; s < STAGES - 1; s++) {
        if (s < nK) issue(s);
        cp_commit();
    }

    for (int kc = 0; kc < nK; kc++) {
        int pf = kc + STAGES - 1;
        if (pf < nK) issue(pf);
        cp_commit();
        cp_wait<STAGES - 1>();
        __syncthreads();

        int s = kc % STAGES;
        const __nv_bfloat16* Ah_s = smem + s * GSTRIDE;
        const __nv_bfloat16* Al_s = Ah_s + GASZ;
        const __nv_bfloat16* Bh_s = Ah_s + 2 * GASZ;
        const __nv_bfloat16* Bl_s = Bh_s + GBSZ;

#pragma unroll
        for (int ks = 0; ks < GBK / 16; ks++) {
            uint32_t af[MT][4], al_[MT][4];
#pragma unroll
            for (int mt = 0; mt < MT; mt++) {
                int row = wm0 + mt * 16 + (lane & 15);
                int col = ks * 16 + (lane >> 4) * 8;
                ldsm4(af[mt][0], af[mt][1], af[mt][2], af[mt][3],
                      smem_u32(&Ah_s[row * GSA + col]));
                ldsm4(al_[mt][0], al_[mt][1], al_[mt][2], al_[mt][3],
                      smem_u32(&Al_s[row * GSA + col]));
            }
            uint32_t bfr[NT][2], blr[NT][2];
#pragma unroll
            for (int ntp = 0; ntp < NTP; ntp++) {
                int g = lane >> 3;
                int noff = (g >> 1) * 8;
                int koff = (g & 1) * 8;
                uint32_t r0, r1, r2, r3;
                int row = wn0 + ntp * 16 + noff + (lane & 7);
                int col = ks * 16 + koff;
                ldsm4(r0, r1, r2, r3, smem_u32(&Bh_s[row * GSA + col]));
                bfr[2 * ntp][0] = r0; bfr[2 * ntp][1] = r1;
                bfr[2 * ntp + 1][0] = r2; bfr[2 * ntp + 1][1] = r3;
                ldsm4(r0, r1, r2, r3, smem_u32(&Bl_s[row * GSA + col]));
                blr[2 * ntp][0] = r0; blr[2 * ntp][1] = r1;
                blr[2 * ntp + 1][0] = r2; blr[2 * ntp + 1][1] = r3;
            }
#pragma unroll
            for (int mt = 0; mt < MT; mt++)
#pragma unroll
                for (int nt = 0; nt < NT; nt++) {
                    mma_bf16(acc[mt][nt], af[mt], bfr[nt]);
                    mma_bf16(acc[mt][nt], af[mt], blr[nt]);
                    mma_bf16(acc[mt][nt], al_[mt], bfr[nt]);
                }
        }
        __syncthreads();
    }

#pragma unroll
    for (int mt = 0; mt < MT; mt++)
#pragma unroll
        for (int nt = 0; nt < NT; nt++) {
            int row = m0 + wm0 + mt * 16 + (lane >> 2);
            int col = n0 + wn0 + nt * 8 + (lane & 3) * 2;
            float bx = bias[col], by = bias[col + 1];
            float v0x = acc[mt][nt][0] + bx;
            float v0y = acc[mt][nt][1] + by;
            float v1x = acc[mt][nt][2] + bx;
            float v1y = acc[mt][nt][3] + by;
            if constexpr (SPLITOUT) {
                uint32_t hh, ll;
                split2(v0x, v0y, hh, ll);
                *(uint32_t*)&Ch[(long)row * D_ + col] = hh;
                *(uint32_t*)&Cl[(long)row * D_ + col] = ll;
                split2(v1x, v1y, hh, ll);
                *(uint32_t*)&Ch[(long)(row + 8) * D_ + col] = hh;
                *(uint32_t*)&Cl[(long)(row + 8) * D_ + col] = ll;
            } else {
                *(float2*)&C[(long)row * D_ + col] = make_float2(v0x, v0y);
                *(float2*)&C[(long)(row + 8) * D_ + col] = make_float2(v1x, v1y);
            }
        }
}

// ---------------- merged Q/K/V projection ----------------------------------
__global__ void __launch_bounds__(256) qkv_proj(
    const __nv_bfloat16* __restrict__ qh, const __nv_bfloat16* __restrict__ ql,
    const __nv_bfloat16* __restrict__ kh, const __nv_bfloat16* __restrict__ kl,
    const __nv_bfloat16* __restrict__ vh, const __nv_bfloat16* __restrict__ vl,
    const __nv_bfloat16* __restrict__ wh, const __nv_bfloat16* __restrict__ wl,
    const float* __restrict__ bq, const float* __restrict__ bk,
    const float* __restrict__ bv,
    __nv_bfloat16* __restrict__ Qh, __nv_bfloat16* __restrict__ Ql,
    __nv_bfloat16* __restrict__ Kh, __nv_bfloat16* __restrict__ Kl,
    __nv_bfloat16* __restrict__ Vh, __nv_bfloat16* __restrict__ Vl) {
    extern __shared__ __nv_bfloat16 smem[];
    int yb = blockIdx.y;
    const __nv_bfloat16 *Ah, *Al, *Bh, *Bl;
    const float* bias;
    __nv_bfloat16 *Ch, *Cl;
    int m0;
    if (yb < 32)       { Ah = qh; Al = ql; Bh = wh;          Bl = wl;          bias = bq; Ch = Qh; Cl = Ql; m0 = yb * 128; }
    else if (yb < 160) { Ah = kh; Al = kl; Bh = wh + DD;     Bl = wl + DD;     bias = bk; Ch = Kh; Cl = Kl; m0 = (yb - 32) * 128; }
    else               { Ah = vh; Al = vl; Bh = wh + 2 * DD; Bl = wl + 2 * DD; bias = bv; Ch = Vh; Cl = Vl; m0 = (yb - 160) * 128; }
    gemm_body<true>(smem, Ah, Al, Bh, Bl, bias, nullptr, Ch, Cl,
                    m0, blockIdx.x * 128);
}

// ---------------- out projection -------------------------------------------
__global__ void __launch_bounds__(256) out_proj(
    const __nv_bfloat16* __restrict__ ch, const __nv_bfloat16* __restrict__ cl,
    const __nv_bfloat16* __restrict__ wh, const __nv_bfloat16* __restrict__ wl,
    const float* __restrict__ bo, float* __restrict__ out) {
    extern __shared__ __nv_bfloat16 smem[];
    gemm_body<false>(smem, ch, cl, wh + 3 * DD, wl + 3 * DD, bo, out,
                     nullptr, nullptr, blockIdx.y * 128, blockIdx.x * 128);
}

// ---------------- fused flash-style attention (3 CTAs/SM) -------------------
// CTA = 128 threads (4 warps), 64 q-rows; K chunks of 64; mask bits from L2.
#define QR_ 64
#define CH_ 64
#define KROW_ 72
#define KSZB_ (CH_ * KROW_ * 2)          // 9216 bytes per K/V buffer
#define STAGEB_ (4 * KSZB_)              // 36864
#define FUSED_SMEM (2 * STAGEB_)         // 73728 -> 3 CTAs/SM

__global__ void __launch_bounds__(128, 3) fused_attn(
    const __nv_bfloat16* __restrict__ Qh, const __nv_bfloat16* __restrict__ Ql,
    const __nv_bfloat16* __restrict__ Kh, const __nv_bfloat16* __restrict__ Kl,
    const __nv_bfloat16* __restrict__ Vh, const __nv_bfloat16* __restrict__ Vl,
    const unsigned long long* __restrict__ maskb, float* __restrict__ attn,
    __nv_bfloat16* __restrict__ Ch, __nv_bfloat16* __restrict__ Cl) {
    extern __shared__ char smc[];
    uint32_t sb = smem_u32(smc);

    int z = blockIdx.y;
    int b = z >> 3, h = z & 7;
    int q0 = blockIdx.x * QR_;
    int tid = threadIdx.x;
    int lane = tid & 31;
    int w = tid >> 5;           // 0..3
    int lr = lane >> 2;
    int lq = lane & 3;

    const __nv_bfloat16* Qbh = Qh + ((long)(b * N_ + q0)) * D_ + h * DK_;
    const __nv_bfloat16* Qbl = Ql + ((long)(b * N_ + q0)) * D_ + h * DK_;
    const __nv_bfloat16* Kbh = Kh + (long)b * HW_ * D_ + h * DK_;
    const __nv_bfloat16* Kbl = Kl + (long)b * HW_ * D_ + h * DK_;
    const __nv_bfloat16* Vbh = Vh + (long)b * HW_ * D_ + h * DK_;
    const __nv_bfloat16* Vbl = Vl + (long)b * HW_ * D_ + h * DK_;
    // per-thread mask rows (uint64 per 64-col chunk)
    const unsigned long long* mb0 = maskb + (long)(q0 + w * 16 + lr) * (HW_ / 64);
    const unsigned long long* mb1 = mb0 + 8 * (HW_ / 64);
    float* attn_z = attn + ((long)z * N_ + q0) * HW_;

    // ---- stage Q (64x64 hi/lo) into buffer0, load fragments ----
    for (int i = tid; i < QR_ * 8; i += 128) {
        int r = i >> 3;
        int c = (i & 7) * 8;
        cp16(sb + (uint32_t)(r * KROW_ + c) * 2, Qbh + (long)r * D_ + c);
        cp16(sb + KSZB_ + (uint32_t)(r * KROW_ + c) * 2, Qbl + (long)r * D_ + c);
    }
    cp_commit();
    cp_wait<0>();
    __syncthreads();

    uint32_t qfh[4][4], qfl[4][4];
#pragma unroll
    for (int ks = 0; ks < 4; ks++) {
        int row = w * 16 + (lane & 15);
        int col = ks * 16 + (lane >> 4) * 8;
        ldsm4(qfh[ks][0], qfh[ks][1], qfh[ks][2], qfh[ks][3],
              sb + (uint32_t)(row * KROW_ + col) * 2);
        ldsm4(qfl[ks][0], qfl[ks][1], qfl[ks][2], qfl[ks][3],
              sb + KSZB_ + (uint32_t)(row * KROW_ + col) * 2);
    }
    __syncthreads();

    auto issue_kv = [&](int kc, bool with_v) {
        uint32_t base = sb + (uint32_t)((kc & 1) * STAGEB_);
        int mc = kc * CH_;
        for (int i = tid; i < CH_ * 8; i += 128) {
            int r = i >> 3;
            int c = (i & 7) * 8;
            long go = (long)(mc + r) * D_ + c;
            uint32_t so = (uint32_t)(r * KROW_ + c) * 2;
            cp16(base + so, Kbh + go);
            cp16(base + KSZB_ + so, Kbl + go);
            if (with_v) {
                cp16(base + 2 * KSZB_ + so, Vbh + go);
                cp16(base + 3 * KSZB_ + so, Vbl + go);
            }
        }
    };

    float ctx[8][4];
#pragma unroll
    for (int j = 0; j < 8; j++)
#pragma unroll
        for (int q = 0; q < 4; q++) ctx[j][q] = 0.0f;
    float rs0 = 0.0f, rs1 = 0.0f;
    float sacc[8][4];

    // ========== PASS 1: rowsums + ctx ==========
    issue_kv(0, true);
    cp_commit();
    for (int kc = 0; kc < HW_ / CH_; kc++) {
        unsigned long long m64a = mb0[kc];   // hoisted mask loads (L2)
        unsigned long long m64b = mb1[kc];
        if (kc + 1 < HW_ / CH_) {
            issue_kv(kc + 1, true);
            cp_commit();
            cp_wait<1>();
        } else {
            cp_wait<0>();
        }
        __syncthreads();

        uint32_t base = sb + (uint32_t)((kc & 1) * STAGEB_);
        uint32_t kh_b = base, kl_b = base + KSZB_;
        uint32_t vh_b = base + 2 * KSZB_, vl_b = base + 3 * KSZB_;

#pragma unroll
        for (int nt = 0; nt < 8; nt++)
#pragma unroll
            for (int q = 0; q < 4; q++) sacc[nt][q] = 0.0f;

        // S = Q @ K^T  (64 q x 64 k)
#pragma unroll
        for (int ks = 0; ks < 4; ks++) {
#pragma unroll
            for (int ntp = 0; ntp < 4; ntp++) {
                int g = lane >> 3;
                int row = ntp * 16 + (g >> 1) * 8 + (lane & 7);
                int col = ks * 16 + (g & 1) * 8;
                uint32_t h0, h1, h2, h3, l0, l1, l2, l3;
                ldsm4(h0, h1, h2, h3, kh_b + (uint32_t)(row * KROW_ + col) * 2);
                ldsm4(l0, l1, l2, l3, kl_b + (uint32_t)(row * KROW_ + col) * 2);
                mma2(sacc[2 * ntp], qfh[ks], h0, h1);
                mma2(sacc[2 * ntp], qfh[ks], l0, l1);
                mma2(sacc[2 * ntp], qfl[ks], h0, h1);
                mma2(sacc[2 * ntp + 1], qfh[ks], h2, h3);
                mma2(sacc[2 * ntp + 1], qfh[ks], l2, l3);
                mma2(sacc[2 * ntp + 1], qfl[ks], h2, h3);
            }
        }

        // mask + exp + rowsum
#pragma unroll
        for (int nt = 0; nt < 8; nt++) {
            int bit = nt * 8 + lq * 2;
            float e0 = ((m64a >> bit) & 1) ? __expf(sacc[nt][0] * 0.125f) : 0.0f;
            float e1 = ((m64a >> (bit + 1)) & 1) ? __expf(sacc[nt][1] * 0.125f) : 0.0f;
            float e2 = ((m64b >> bit) & 1) ? __expf(sacc[nt][2] * 0.125f) : 0.0f;
            float e3 = ((m64b >> (bit + 1)) & 1) ? __expf(sacc[nt][3] * 0.125f) : 0.0f;
            rs0 += e0 + e1;
            rs1 += e2 + e3;
            sacc[nt][0] = e0; sacc[nt][1] = e1;
            sacc[nt][2] = e2; sacc[nt][3] = e3;
        }

        // ctx += E @ V
#pragma unroll
        for (int kt = 0; kt < 4; kt++) {
            uint32_t ah[4], al_[4];
            split2(sacc[2 * kt][0], sacc[2 * kt][1], ah[0], al_[0]);
            split2(sacc[2 * kt][2], sacc[2 * kt][3], ah[1], al_[1]);
            split2(sacc[2 * kt + 1][0], sacc[2 * kt + 1][1], ah[2], al_[2]);
            split2(sacc[2 * kt + 1][2], sacc[2 * kt + 1][3], ah[3], al_[3]);
#pragma unroll
            for (int ntp = 0; ntp < 4; ntp++) {
                int g = lane >> 3;
                int row = kt * 16 + (g & 1) * 8 + (lane & 7);
                int col = ntp * 16 + (g >> 1) * 8;
                uint32_t h0, h1, h2, h3, l0, l1, l2, l3;
                ldsm4t(h0, h1, h2, h3, vh_b + (uint32_t)(row * KROW_ + col) * 2);
                ldsm4t(l0, l1, l2, l3, vl_b + (uint32_t)(row * KROW_ + col) * 2);
                mma2(ctx[2 * ntp], ah, h0, h1);
                mma2(ctx[2 * ntp], ah, l0, l1);
                mma2(ctx[2 * ntp], al_, h0, h1);
                mma2(ctx[2 * ntp + 1], ah, h2, h3);
                mma2(ctx[2 * ntp + 1], ah, l2, l3);
                mma2(ctx[2 * ntp + 1], al_, h2, h3);
            }
        }
        __syncthreads();
    }

    rs0 += __shfl_xor_sync(0xffffffffu, rs0, 1);
    rs0 += __shfl_xor_sync(0xffffffffu, rs0, 2);
    rs1 += __shfl_xor_sync(0xffffffffu, rs1, 1);
    rs1 += __shfl_xor_sync(0xffffffffu, rs1, 2);
    float inv0 = 1.0f / rs0;
    float inv1 = 1.0f / rs1;

    // scale + write ctx (split bf16)
#pragma unroll
    for (int nt = 0; nt < 8; nt++) {
        int row = w * 16 + lr;
        int col = nt * 8 + lq * 2;
        long off = ((long)(b * N_ + q0 + row)) * D_ + h * DK_ + col;
        uint32_t hh, ll;
        split2(ctx[nt][0] * inv0, ctx[nt][1] * inv0, hh, ll);
        *(uint32_t*)&Ch[off] = hh;
        *(uint32_t*)&Cl[off] = ll;
        split2(ctx[nt][2] * inv1, ctx[nt][3] * inv1, hh, ll);
        *(uint32_t*)&Ch[off + 8 * D_] = hh;
        *(uint32_t*)&Cl[off + 8 * D_] = ll;
    }

    // ========== PASS 2: recompute S, write normalized attn ==========
    issue_kv(0, false);
    cp_commit();
    for (int kc = 0; kc < HW_ / CH_; kc++) {
        unsigned long long m64a = mb0[kc];
        unsigned long long m64b = mb1[kc];
        if (kc + 1 < HW_ / CH_) {
            issue_kv(kc + 1, false);
            cp_commit();
            cp_wait<1>();
        } else {
            cp_wait<0>();
        }
        __syncthreads();

        uint32_t base = sb + (uint32_t)((kc & 1) * STAGEB_);
        uint32_t kh_b = base, kl_b = base + KSZB_;
        int mc = kc * CH_;

#pragma unroll
        for (int nt = 0; nt < 8; nt++)
#pragma unroll
            for (int q = 0; q < 4; q++) sacc[nt][q] = 0.0f;

#pragma unroll
        for (int ks = 0; ks < 4; ks++) {
#pragma unroll
            for (int ntp = 0; ntp < 4; ntp++) {
                int g = lane >> 3;
                int row = ntp * 16 + (g >> 1) * 8 + (lane & 7);
                int col = ks * 16 + (g & 1) * 8;
                uint32_t h0, h1, h2, h3, l0, l1, l2, l3;
                ldsm4(h0, h1, h2, h3, kh_b + (uint32_t)(row * KROW_ + col) * 2);
                ldsm4(l0, l1, l2, l3, kl_b + (uint32_t)(row * KROW_ + col) * 2);
                mma2(sacc[2 * ntp], qfh[ks], h0, h1);
                mma2(sacc[2 * ntp], qfh[ks], l0, l1);
                mma2(sacc[2 * ntp], qfl[ks], h0, h1);
                mma2(sacc[2 * ntp + 1], qfh[ks], h2, h3);
                mma2(sacc[2 * ntp + 1], qfh[ks], l2, l3);
                mma2(sacc[2 * ntp + 1], qfl[ks], h2, h3);
            }
        }

        int grow0 = w * 16 + lr;
#pragma unroll
        for (int nt = 0; nt < 8; nt++) {
            int bit = nt * 8 + lq * 2;
            float e0 = ((m64a >> bit) & 1) ? __expf(sacc[nt][0] * 0.125f) * inv0 : 0.0f;
            float e1 = ((m64a >> (bit + 1)) & 1) ? __expf(sacc[nt][1] * 0.125f) * inv0 : 0.0f;
            float e2 = ((m64b >> bit) & 1) ? __expf(sacc[nt][2] * 0.125f) * inv1 : 0.0f;
            float e3 = ((m64b >> (bit + 1)) & 1) ? __expf(sacc[nt][3] * 0.125f) * inv1 : 0.0f;
            int col = mc + nt * 8 + lq * 2;
            *(float2*)(attn_z + (long)grow0 * HW_ + col) = make_float2(e0, e1);
            *(float2*)(attn_z + (long)(grow0 + 8) * HW_ + col) = make_float2(e2, e3);
        }
        __syncthreads();
    }
}

// ---------------- launch ---------------------------------------------------
extern "C" void kernel_launch(void* const* d_in, const int* in_sizes, int n_in,
                              void* d_out, int out_size) {
    const float* query   = (const float*)d_in[0];
    const float* key     = (const float*)d_in[1];
    const float* value   = (const float*)d_in[2];
    const float* x_tilde = (const float*)d_in[3];
    const float* x_hat   = (const float*)d_in[4];
    const float* Wq = (const float*)d_in[5];
    const float* bq = (const float*)d_in[6];
    const float* Wk = (const float*)d_in[7];
    const float* bk = (const float*)d_in[8];
    const float* Wv = (const float*)d_in[9];
    const float* bv = (const float*)d_in[10];
    const float* Wo = (const float*)d_in[11];
    const float* bo = (const float*)d_in[12];

    float* out = (float*)d_out;
    float* attn = out + (size_t)B_ * N_ * D_;

    __nv_bfloat16 *qh, *ql, *kh, *kl, *vh, *vl, *wh, *wl;
    __nv_bfloat16 *Qh, *Ql, *Kh, *Kl, *Vh, *Vl, *ch, *cl;
    unsigned long long* Mb;
    cudaGetSymbolAddress((void**)&qh, g_qh);   cudaGetSymbolAddress((void**)&ql, g_ql);
    cudaGetSymbolAddress((void**)&kh, g_kh);   cudaGetSymbolAddress((void**)&kl, g_kl);
    cudaGetSymbolAddress((void**)&vh, g_vh);   cudaGetSymbolAddress((void**)&vl, g_vl);
    cudaGetSymbolAddress((void**)&wh, g_wh);   cudaGetSymbolAddress((void**)&wl, g_wl);
    cudaGetSymbolAddress((void**)&Qh, g_Qh);   cudaGetSymbolAddress((void**)&Ql, g_Ql);
    cudaGetSymbolAddress((void**)&Kh, g_Kh);   cudaGetSymbolAddress((void**)&Kl, g_Kl);
    cudaGetSymbolAddress((void**)&Vh, g_Vh);   cudaGetSymbolAddress((void**)&Vl, g_Vl);
    cudaGetSymbolAddress((void**)&ch, g_ctxh); cudaGetSymbolAddress((void**)&cl, g_ctxl);
    cudaGetSymbolAddress((void**)&Mb, g_maskb);

    cudaFuncSetAttribute(qkv_proj, cudaFuncAttributeMaxDynamicSharedMemorySize, SMEM_BIG);
    cudaFuncSetAttribute(out_proj, cudaFuncAttributeMaxDynamicSharedMemorySize, SMEM_BIG);
    cudaFuncSetAttribute(fused_attn, cudaFuncAttributeMaxDynamicSharedMemorySize,
                         FUSED_SMEM);

    // launch 0: mask (bit-packed)
    mask_kernel<<<(N_ * HW_ + 255) / 256, 256>>>(x_tilde, x_hat, (unsigned int*)Mb);

    // launch 1: all splits
    split_all<<<(NTOT4 + 255) / 256, 256>>>(
        (const float4*)query, (const float4*)key, (const float4*)value,
        (const float4*)Wq, (const float4*)Wk, (const float4*)Wv, (const float4*)Wo,
        (uint2*)qh, (uint2*)ql, (uint2*)kh, (uint2*)kl, (uint2*)vh, (uint2*)vl,
        (uint2*)wh, (uint2*)wl);

    // launch 2: merged Q/K/V projections
    qkv_proj<<<dim3(4, 288), 256, SMEM_BIG>>>(qh, ql, kh, kl, vh, vl, wh, wl,
                                              bq, bk, bv, Qh, Ql, Kh, Kl, Vh, Vl);

    // launch 3: fused attention (3 CTAs/SM target)
    fused_attn<<<dim3(N_ / QR_, ZTOT), 128, FUSED_SMEM>>>(
        Qh, Ql, Kh, Kl, Vh, Vl, Mb, attn, ch, cl);

    // launch 4: out projection
    out_proj<<<dim3(4, 32), 256, SMEM_BIG>>>(ch, cl, wh, wl, bo, out);
}

// round 13
// speedup vs baseline: 1.7880x; 1.7880x over previous
#include <cuda_runtime.h>
#include <cuda_bf16.h>
#include <math.h>
#include <stdint.h>

#define B_ 4
#define N_ 1024
#define HW_ 4096
#define D_ 512
#define H_ 8
#define DK_ 64
#define ZTOT (B_ * H_)
#define DD (D_ * D_)

// ---------------- scratch (static device globals; no allocation) -----------
__device__ __nv_bfloat16 g_qh[B_ * N_ * D_],  g_ql[B_ * N_ * D_];
__device__ __nv_bfloat16 g_kh[B_ * HW_ * D_], g_kl[B_ * HW_ * D_];
__device__ __nv_bfloat16 g_vh[B_ * HW_ * D_], g_vl[B_ * HW_ * D_];
__device__ __nv_bfloat16 g_wh[4 * DD], g_wl[4 * DD];
__device__ __nv_bfloat16 g_Qh[B_ * N_ * D_],  g_Ql[B_ * N_ * D_];
__device__ __nv_bfloat16 g_Kh[B_ * HW_ * D_], g_Kl[B_ * HW_ * D_];
__device__ __nv_bfloat16 g_Vh[B_ * HW_ * D_], g_Vl[B_ * HW_ * D_];
__device__ __nv_bfloat16 g_ctxh[B_ * N_ * D_], g_ctxl[B_ * N_ * D_];
__device__ unsigned long long g_maskb[(size_t)N_ * HW_ / 64];   // bit-packed mask

// ---------------- helpers --------------------------------------------------
__device__ __forceinline__ uint32_t smem_u32(const void* p) {
    return (uint32_t)__cvta_generic_to_shared(p);
}
__device__ __forceinline__ void cp16(uint32_t s, const void* g) {
    asm volatile("cp.async.cg.shared.global [%0],[%1],16;" :: "r"(s), "l"(g));
}
__device__ __forceinline__ void cp_commit() {
    asm volatile("cp.async.commit_group;" ::: "memory");
}
template <int NN>
__device__ __forceinline__ void cp_wait() {
    asm volatile("cp.async.wait_group %0;" :: "n"(NN) : "memory");
}
__device__ __forceinline__ void ldsm4(uint32_t& r0, uint32_t& r1, uint32_t& r2,
                                      uint32_t& r3, uint32_t a) {
    asm volatile("ldmatrix.sync.aligned.m8n8.x4.shared.b16 {%0,%1,%2,%3},[%4];"
                 : "=r"(r0), "=r"(r1), "=r"(r2), "=r"(r3) : "r"(a));
}
__device__ __forceinline__ void ldsm4t(uint32_t& r0, uint32_t& r1, uint32_t& r2,
                                       uint32_t& r3, uint32_t a) {
    asm volatile("ldmatrix.sync.aligned.m8n8.x4.trans.shared.b16 {%0,%1,%2,%3},[%4];"
                 : "=r"(r0), "=r"(r1), "=r"(r2), "=r"(r3) : "r"(a));
}
__device__ __forceinline__ void mma_bf16(float* c, const uint32_t* a, const uint32_t* b) {
    asm volatile(
        "mma.sync.aligned.m16n8k16.row.col.f32.bf16.bf16.f32 "
        "{%0,%1,%2,%3},{%4,%5,%6,%7},{%8,%9},{%0,%1,%2,%3};"
        : "+f"(c[0]), "+f"(c[1]), "+f"(c[2]), "+f"(c[3])
        : "r"(a[0]), "r"(a[1]), "r"(a[2]), "r"(a[3]), "r"(b[0]), "r"(b[1]));
}
__device__ __forceinline__ void mma2(float* c, const uint32_t* a, uint32_t b0, uint32_t b1) {
    uint32_t b[2] = {b0, b1};
    mma_bf16(c, a, b);
}
__device__ __forceinline__ void split2(float x, float y, uint32_t& hi, uint32_t& lo) {
    __nv_bfloat16 hx = __float2bfloat16(x);
    __nv_bfloat16 hy = __float2bfloat16(y);
    __nv_bfloat16 lx = __float2bfloat16(x - __bfloat162float(hx));
    __nv_bfloat16 ly = __float2bfloat16(y - __bfloat162float(hy));
    hi = (uint32_t)__bfloat16_as_ushort(hx) | ((uint32_t)__bfloat16_as_ushort(hy) << 16);
    lo = (uint32_t)__bfloat16_as_ushort(lx) | ((uint32_t)__bfloat16_as_ushort(ly) << 16);
}

// ---------------- single merged split kernel -------------------------------
#define NQ4 (B_ * N_ * D_ / 4)
#define NK4 (B_ * HW_ * D_ / 4)
#define NV4 NK4
#define NW4 DD
#define NTOT4 (NQ4 + NK4 + NV4 + NW4)

__global__ void split_all(const float4* __restrict__ q, const float4* __restrict__ k,
                          const float4* __restrict__ v,
                          const float4* __restrict__ W0, const float4* __restrict__ W1,
                          const float4* __restrict__ W2, const float4* __restrict__ W3,
                          uint2* __restrict__ qh, uint2* __restrict__ ql,
                          uint2* __restrict__ kh, uint2* __restrict__ kl,
                          uint2* __restrict__ vh, uint2* __restrict__ vl,
                          uint2* __restrict__ wh, uint2* __restrict__ wl) {
    int i = blockIdx.x * blockDim.x + threadIdx.x;
    if (i >= NTOT4) return;
    float4 vv;
    uint2 *Hd, *Ld;
    int j;
    if (i < NQ4) { j = i; vv = q[j]; Hd = qh; Ld = ql; }
    else if (i < NQ4 + NK4) { j = i - NQ4; vv = k[j]; Hd = kh; Ld = kl; }
    else if (i < NQ4 + NK4 + NV4) { j = i - NQ4 - NK4; vv = v[j]; Hd = vh; Ld = vl; }
    else {
        j = i - NQ4 - NK4 - NV4;
        int a = j >> 16;
        int r = j & 0xFFFF;
        vv = (a == 0 ? W0 : a == 1 ? W1 : a == 2 ? W2 : W3)[r];
        Hd = wh; Ld = wl;
    }
    uint32_t h0, l0, h1, l1;
    split2(vv.x, vv.y, h0, l0);
    split2(vv.z, vv.w, h1, l1);
    Hd[j] = make_uint2(h0, h1);
    Ld[j] = make_uint2(l0, l1);
}

// ---------------- mask precompute (bit-packed via ballot) ------------------
__global__ void mask_kernel(const float* __restrict__ x_tilde,
                            const float* __restrict__ x_hat,
                            unsigned int* __restrict__ maskb) {
    int idx = blockIdx.x * blockDim.x + threadIdx.x;
    int m = idx & (HW_ - 1);
    float dx = x_tilde[m * 2 + 0] - x_hat[(size_t)idx * 2 + 0];
    float dy = x_tilde[m * 2 + 1] - x_hat[(size_t)idx * 2 + 1];
    unsigned keep = (sqrtf(dx * dx + dy * dy) < 0.1f) ? 1u : 0u;
    unsigned bal = __ballot_sync(0xffffffffu, keep);
    if ((idx & 31) == 0) maskb[idx >> 5] = bal;
}

// ---------------- shared GEMM body (128x128 tile, K=512, split-bf16) -------
#define GBM 128
#define GBN 128
#define GBK 32
#define GSA (GBK + 8)
#define GASZ (GBM * GSA)
#define GBSZ (GBN * GSA)
#define GSTRIDE (2 * GASZ + 2 * GBSZ)
#define SMEM_BIG (3 * GSTRIDE * 2)

template <bool SPLITOUT>
__device__ __forceinline__ void gemm_body(
    __nv_bfloat16* smem,
    const __nv_bfloat16* __restrict__ Agh, const __nv_bfloat16* __restrict__ Agl,
    const __nv_bfloat16* __restrict__ Bgh, const __nv_bfloat16* __restrict__ Bgl,
    const float* __restrict__ bias, float* __restrict__ C,
    __nv_bfloat16* __restrict__ Ch, __nv_bfloat16* __restrict__ Cl,
    int m0, int n0) {
    constexpr int STAGES = 3;
    constexpr int WM = 64, WN = 32;
    constexpr int WNC = GBN / WN;
    constexpr int MT = WM / 16;
    constexpr int NT = WN / 8;
    constexpr int NTP = NT / 2;

    int tid = threadIdx.x;
    int lane = tid & 31;
    int wid = tid >> 5;
    int wm0 = (wid / WNC) * WM;
    int wn0 = (wid % WNC) * WN;

    const int nK = D_ / GBK;
    uint32_t smem_b = smem_u32(smem);

    auto issue = [&](int kc) {
        int s = kc % STAGES;
        int k0 = kc * GBK;
        uint32_t base = smem_b + (uint32_t)(s * GSTRIDE) * 2;
        for (int i = tid; i < GBM * (GBK / 8); i += 256) {
            int r = i / (GBK / 8);
            int c = (i % (GBK / 8)) * 8;
            long go = (long)(m0 + r) * D_ + k0 + c;
            uint32_t so = (uint32_t)(r * GSA + c) * 2;
            cp16(base + so, Agh + go);
            cp16(base + (uint32_t)GASZ * 2 + so, Agl + go);
        }
        uint32_t bb = base + (uint32_t)(2 * GASZ) * 2;
        for (int i = tid; i < GBN * (GBK / 8); i += 256) {
            int r = i / (GBK / 8);
            int c = (i % (GBK / 8)) * 8;
            long go = (long)(n0 + r) * D_ + k0 + c;
            uint32_t so = (uint32_t)(r * GSA + c) * 2;
            cp16(bb + so, Bgh + go);
            cp16(bb + (uint32_t)GBSZ * 2 + so, Bgl + go);
        }
    };

    float acc[MT][NT][4];
#pragma unroll
    for (int i = 0; i < MT; i++)
#pragma unroll
        for (int j = 0; j < NT; j++)
#pragma unroll
            for (int q = 0; q < 4; q++) acc[i][j][q] = 0.0f;

    for (int s = 0; s < STAGES - 1; s++) {
        if (s < nK) issue(s);
        cp_commit();
    }

    for (int kc = 0; kc < nK; kc++) {
        int pf = kc + STAGES - 1;
        if (pf < nK) issue(pf);
        cp_commit();
        cp_wait<STAGES - 1>();
        __syncthreads();

        int s = kc % STAGES;
        const __nv_bfloat16* Ah_s = smem + s * GSTRIDE;
        const __nv_bfloat16* Al_s = Ah_s + GASZ;
        const __nv_bfloat16* Bh_s = Ah_s + 2 * GASZ;
        const __nv_bfloat16* Bl_s = Bh_s + GBSZ;

#pragma unroll
        for (int ks = 0; ks < GBK / 16; ks++) {
            uint32_t af[MT][4], al_[MT][4];
#pragma unroll
            for (int mt = 0; mt < MT; mt++) {
                int row = wm0 + mt * 16 + (lane & 15);
                int col = ks * 16 + (lane >> 4) * 8;
                ldsm4(af[mt][0], af[mt][1], af[mt][2], af[mt][3],
                      smem_u32(&Ah_s[row * GSA + col]));
                ldsm4(al_[mt][0], al_[mt][1], al_[mt][2], al_[mt][3],
                      smem_u32(&Al_s[row * GSA + col]));
            }
            uint32_t bfr[NT][2], blr[NT][2];
#pragma unroll
            for (int ntp = 0; ntp < NTP; ntp++) {
                int g = lane >> 3;
                int noff = (g >> 1) * 8;
                int koff = (g & 1) * 8;
                uint32_t r0, r1, r2, r3;
                int row = wn0 + ntp * 16 + noff + (lane & 7);
                int col = ks * 16 + koff;
                ldsm4(r0, r1, r2, r3, smem_u32(&Bh_s[row * GSA + col]));
                bfr[2 * ntp][0] = r0; bfr[2 * ntp][1] = r1;
                bfr[2 * ntp + 1][0] = r2; bfr[2 * ntp + 1][1] = r3;
                ldsm4(r0, r1, r2, r3, smem_u32(&Bl_s[row * GSA + col]));
                blr[2 * ntp][0] = r0; blr[2 * ntp][1] = r1;
                blr[2 * ntp + 1][0] = r2; blr[2 * ntp + 1][1] = r3;
            }
#pragma unroll
            for (int mt = 0; mt < MT; mt++)
#pragma unroll
                for (int nt = 0; nt < NT; nt++) {
                    mma_bf16(acc[mt][nt], af[mt], bfr[nt]);
                    mma_bf16(acc[mt][nt], af[mt], blr[nt]);
                    mma_bf16(acc[mt][nt], al_[mt], bfr[nt]);
                }
        }
        __syncthreads();
    }

#pragma unroll
    for (int mt = 0; mt < MT; mt++)
#pragma unroll
        for (int nt = 0; nt < NT; nt++) {
            int row = m0 + wm0 + mt * 16 + (lane >> 2);
            int col = n0 + wn0 + nt * 8 + (lane & 3) * 2;
            float bx = bias[col], by = bias[col + 1];
            float v0x = acc[mt][nt][0] + bx;
            float v0y = acc[mt][nt][1] + by;
            float v1x = acc[mt][nt][2] + bx;
            float v1y = acc[mt][nt][3] + by;
            if constexpr (SPLITOUT) {
                uint32_t hh, ll;
                split2(v0x, v0y, hh, ll);
                *(uint32_t*)&Ch[(long)row * D_ + col] = hh;
                *(uint32_t*)&Cl[(long)row * D_ + col] = ll;
                split2(v1x, v1y, hh, ll);
                *(uint32_t*)&Ch[(long)(row + 8) * D_ + col] = hh;
                *(uint32_t*)&Cl[(long)(row + 8) * D_ + col] = ll;
            } else {
                *(float2*)&C[(long)row * D_ + col] = make_float2(v0x, v0y);
                *(float2*)&C[(long)(row + 8) * D_ + col] = make_float2(v1x, v1y);
            }
        }
}

// ---------------- merged Q/K/V projection ----------------------------------
__global__ void __launch_bounds__(256) qkv_proj(
    const __nv_bfloat16* __restrict__ qh, const __nv_bfloat16* __restrict__ ql,
    const __nv_bfloat16* __restrict__ kh, const __nv_bfloat16* __restrict__ kl,
    const __nv_bfloat16* __restrict__ vh, const __nv_bfloat16* __restrict__ vl,
    const __nv_bfloat16* __restrict__ wh, const __nv_bfloat16* __restrict__ wl,
    const float* __restrict__ bq, const float* __restrict__ bk,
    const float* __restrict__ bv,
    __nv_bfloat16* __restrict__ Qh, __nv_bfloat16* __restrict__ Ql,
    __nv_bfloat16* __restrict__ Kh, __nv_bfloat16* __restrict__ Kl,
    __nv_bfloat16* __restrict__ Vh, __nv_bfloat16* __restrict__ Vl) {
    extern __shared__ __nv_bfloat16 smem[];
    int yb = blockIdx.y;
    const __nv_bfloat16 *Ah, *Al, *Bh, *Bl;
    const float* bias;
    __nv_bfloat16 *Ch, *Cl;
    int m0;
    if (yb < 32)       { Ah = qh; Al = ql; Bh = wh;          Bl = wl;          bias = bq; Ch = Qh; Cl = Ql; m0 = yb * 128; }
    else if (yb < 160) { Ah = kh; Al = kl; Bh = wh + DD;     Bl = wl + DD;     bias = bk; Ch = Kh; Cl = Kl; m0 = (yb - 32) * 128; }
    else               { Ah = vh; Al = vl; Bh = wh + 2 * DD; Bl = wl + 2 * DD; bias = bv; Ch = Vh; Cl = Vl; m0 = (yb - 160) * 128; }
    gemm_body<true>(smem, Ah, Al, Bh, Bl, bias, nullptr, Ch, Cl,
                    m0, blockIdx.x * 128);
}

// ---------------- out projection -------------------------------------------
__global__ void __launch_bounds__(256) out_proj(
    const __nv_bfloat16* __restrict__ ch, const __nv_bfloat16* __restrict__ cl,
    const __nv_bfloat16* __restrict__ wh, const __nv_bfloat16* __restrict__ wl,
    const float* __restrict__ bo, float* __restrict__ out) {
    extern __shared__ __nv_bfloat16 smem[];
    gemm_body<false>(smem, ch, cl, wh + 3 * DD, wl + 3 * DD, bo, out,
                     nullptr, nullptr, blockIdx.y * 128, blockIdx.x * 128);
}

// ---------------- fused flash-style attention -------------------------------
// Proven R10 geometry: 256 threads, 128 q rows, CH_=128 chunks.
// Mask now bit-packed, read from L2 as u64 per 64 cols (no smem staging).
#define CH_ 128
#define KROW_ 72
#define KSZB_ (CH_ * KROW_ * 2)          // 18432 bytes per K/V buffer
#define STAGEB_ (4 * KSZB_)              // 73728 (no mask buffer)
#define FUSED_SMEM (2 * STAGEB_)         // 147456

__global__ void __launch_bounds__(256) fused_attn(
    const __nv_bfloat16* __restrict__ Qh, const __nv_bfloat16* __restrict__ Ql,
    const __nv_bfloat16* __restrict__ Kh, const __nv_bfloat16* __restrict__ Kl,
    const __nv_bfloat16* __restrict__ Vh, const __nv_bfloat16* __restrict__ Vl,
    const unsigned long long* __restrict__ maskb, float* __restrict__ attn,
    __nv_bfloat16* __restrict__ Ch, __nv_bfloat16* __restrict__ Cl) {
    extern __shared__ char smc[];
    uint32_t sb = smem_u32(smc);

    int z = blockIdx.y;
    int b = z >> 3, h = z & 7;
    int q0 = blockIdx.x * 128;
    int tid = threadIdx.x;
    int lane = tid & 31;
    int w = tid >> 5;
    int lr = lane >> 2;
    int lq = lane & 3;

    const __nv_bfloat16* Qbh = Qh + ((long)(b * N_ + q0)) * D_ + h * DK_;
    const __nv_bfloat16* Qbl = Ql + ((long)(b * N_ + q0)) * D_ + h * DK_;
    const __nv_bfloat16* Kbh = Kh + (long)b * HW_ * D_ + h * DK_;
    const __nv_bfloat16* Kbl = Kl + (long)b * HW_ * D_ + h * DK_;
    const __nv_bfloat16* Vbh = Vh + (long)b * HW_ * D_ + h * DK_;
    const __nv_bfloat16* Vbl = Vl + (long)b * HW_ * D_ + h * DK_;
    // per-thread mask row pointers: rows grow0 and grow0+8, 64 bits per u64
    const unsigned long long* mr0 = maskb + (long)(q0 + w * 16 + lr) * (HW_ / 64);
    const unsigned long long* mr1 = mr0 + 8 * (HW_ / 64);
    float* attn_z = attn + ((long)z * N_ + q0) * HW_;

    // stage Q, load fragments
    for (int i = tid; i < 1024; i += 256) {
        int r = i >> 3;
        int c = (i & 7) * 8;
        cp16(sb + (uint32_t)(r * KROW_ + c) * 2, Qbh + (long)r * D_ + c);
        cp16(sb + KSZB_ + (uint32_t)(r * KROW_ + c) * 2, Qbl + (long)r * D_ + c);
    }
    cp_commit();
    cp_wait<0>();
    __syncthreads();

    uint32_t qfh[4][4], qfl[4][4];
#pragma unroll
    for (int ks = 0; ks < 4; ks++) {
        int row = w * 16 + (lane & 15);
        int col = ks * 16 + (lane >> 4) * 8;
        ldsm4(qfh[ks][0], qfh[ks][1], qfh[ks][2], qfh[ks][3],
              sb + (uint32_t)(row * KROW_ + col) * 2);
        ldsm4(qfl[ks][0], qfl[ks][1], qfl[ks][2], qfl[ks][3],
              sb + KSZB_ + (uint32_t)(row * KROW_ + col) * 2);
    }
    __syncthreads();

    auto issue_kv = [&](int kc, bool with_v) {
        uint32_t base = sb + (uint32_t)((kc & 1) * STAGEB_);
        int mc = kc * CH_;
        for (int i = tid; i < 1024; i += 256) {
            int r = i >> 3;
            int c = (i & 7) * 8;
            long go = (long)(mc + r) * D_ + c;
            uint32_t so = (uint32_t)(r * KROW_ + c) * 2;
            cp16(base + so, Kbh + go);
            cp16(base + KSZB_ + so, Kbl + go);
            if (with_v) {
                cp16(base + 2 * KSZB_ + so, Vbh + go);
                cp16(base + 3 * KSZB_ + so, Vbl + go);
            }
        }
    };

    float ctx[8][4];
#pragma unroll
    for (int j = 0; j < 8; j++)
#pragma unroll
        for (int q = 0; q < 4; q++) ctx[j][q] = 0.0f;
    float rs0 = 0.0f, rs1 = 0.0f;
    float sacc[16][4];

    // ========== PASS 1 ==========
    issue_kv(0, true);
    cp_commit();
    for (int kc = 0; kc < HW_ / CH_; kc++) {
        // mask words for this 128-col chunk (2 u64 per row), L2-resident
        unsigned long long a0 = mr0[2 * kc], a1 = mr0[2 * kc + 1];
        unsigned long long b0_ = mr1[2 * kc], b1_ = mr1[2 * kc + 1];
        if (kc + 1 < HW_ / CH_) {
            issue_kv(kc + 1, true);
            cp_commit();
            cp_wait<1>();
        } else {
            cp_wait<0>();
        }
        __syncthreads();

        uint32_t base = sb + (uint32_t)((kc & 1) * STAGEB_);
        uint32_t kh_b = base, kl_b = base + KSZB_;
        uint32_t vh_b = base + 2 * KSZB_, vl_b = base + 3 * KSZB_;

#pragma unroll
        for (int nt = 0; nt < 16; nt++)
#pragma unroll
            for (int q = 0; q < 4; q++) sacc[nt][q] = 0.0f;

#pragma unroll
        for (int ks = 0; ks < 4; ks++) {
#pragma unroll
            for (int ntp = 0; ntp < 8; ntp++) {
                int g = lane >> 3;
                int row = ntp * 16 + (g >> 1) * 8 + (lane & 7);
                int col = ks * 16 + (g & 1) * 8;
                uint32_t h0, h1, h2, h3, l0, l1, l2, l3;
                ldsm4(h0, h1, h2, h3, kh_b + (uint32_t)(row * KROW_ + col) * 2);
                ldsm4(l0, l1, l2, l3, kl_b + (uint32_t)(row * KROW_ + col) * 2);
                mma2(sacc[2 * ntp], qfh[ks], h0, h1);
                mma2(sacc[2 * ntp], qfh[ks], l0, l1);
                mma2(sacc[2 * ntp], qfl[ks], h0, h1);
                mma2(sacc[2 * ntp + 1], qfh[ks], h2, h3);
                mma2(sacc[2 * ntp + 1], qfh[ks], l2, l3);
                mma2(sacc[2 * ntp + 1], qfl[ks], h2, h3);
            }
        }

        // mask + exp + rowsum (E left in sacc)
#pragma unroll
        for (int nt = 0; nt < 16; nt++) {
            unsigned long long ma = (nt < 8) ? a0 : a1;
            unsigned long long mb = (nt < 8) ? b0_ : b1_;
            int bit = (nt & 7) * 8 + lq * 2;
            float e0 = ((ma >> bit) & 1) ? __expf(sacc[nt][0] * 0.125f) : 0.0f;
            float e1 = ((ma >> (bit + 1)) & 1) ? __expf(sacc[nt][1] * 0.125f) : 0.0f;
            float e2 = ((mb >> bit) & 1) ? __expf(sacc[nt][2] * 0.125f) : 0.0f;
            float e3 = ((mb >> (bit + 1)) & 1) ? __expf(sacc[nt][3] * 0.125f) : 0.0f;
            rs0 += e0 + e1;
            rs1 += e2 + e3;
            sacc[nt][0] = e0; sacc[nt][1] = e1;
            sacc[nt][2] = e2; sacc[nt][3] = e3;
        }

#pragma unroll
        for (int kt = 0; kt < 8; kt++) {
            uint32_t ah[4], al_[4];
            split2(sacc[2 * kt][0], sacc[2 * kt][1], ah[0], al_[0]);
            split2(sacc[2 * kt][2], sacc[2 * kt][3], ah[1], al_[1]);
            split2(sacc[2 * kt + 1][0], sacc[2 * kt + 1][1], ah[2], al_[2]);
            split2(sacc[2 * kt + 1][2], sacc[2 * kt + 1][3], ah[3], al_[3]);
#pragma unroll
            for (int ntp = 0; ntp < 4; ntp++) {
                int g = lane >> 3;
                int row = kt * 16 + (g & 1) * 8 + (lane & 7);
                int col = ntp * 16 + (g >> 1) * 8;
                uint32_t h0, h1, h2, h3, l0, l1, l2, l3;
                ldsm4t(h0, h1, h2, h3, vh_b + (uint32_t)(row * KROW_ + col) * 2);
                ldsm4t(l0, l1, l2, l3, vl_b + (uint32_t)(row * KROW_ + col) * 2);
                mma2(ctx[2 * ntp], ah, h0, h1);
                mma2(ctx[2 * ntp], ah, l0, l1);
                mma2(ctx[2 * ntp], al_, h0, h1);
                mma2(ctx[2 * ntp + 1], ah, h2, h3);
                mma2(ctx[2 * ntp + 1], ah, l2, l3);
                mma2(ctx[2 * ntp + 1], al_, h2, h3);
            }
        }
        __syncthreads();
    }

    rs0 += __shfl_xor_sync(0xffffffffu, rs0, 1);
    rs0 += __shfl_xor_sync(0xffffffffu, rs0, 2);
    rs1 += __shfl_xor_sync(0xffffffffu, rs1, 1);
    rs1 += __shfl_xor_sync(0xffffffffu, rs1, 2);
    float inv0 = 1.0f / rs0;
    float inv1 = 1.0f / rs1;

#pragma unroll
    for (int nt = 0; nt < 8; nt++) {
        int row = w * 16 + lr;
        int col = nt * 8 + lq * 2;
        long off = ((long)(b * N_ + q0 + row)) * D_ + h * DK_ + col;
        uint32_t hh, ll;
        split2(ctx[nt][0] * inv0, ctx[nt][1] * inv0, hh, ll);
        *(uint32_t*)&Ch[off] = hh;
        *(uint32_t*)&Cl[off] = ll;
        split2(ctx[nt][2] * inv1, ctx[nt][3] * inv1, hh, ll);
        *(uint32_t*)&Ch[off + 8 * D_] = hh;
        *(uint32_t*)&Cl[off + 8 * D_] = ll;
    }

    // ========== PASS 2 ==========
    issue_kv(0, false);
    cp_commit();
    for (int kc = 0; kc < HW_ / CH_; kc++) {
        unsigned long long a0 = mr0[2 * kc], a1 = mr0[2 * kc + 1];
        unsigned long long b0_ = mr1[2 * kc], b1_ = mr1[2 * kc + 1];
        if (kc + 1 < HW_ / CH_) {
            issue_kv(kc + 1, false);
            cp_commit();
            cp_wait<1>();
        } else {
            cp_wait<0>();
        }
        __syncthreads();

        uint32_t base = sb + (uint32_t)((kc & 1) * STAGEB_);
        uint32_t kh_b = base, kl_b = base + KSZB_;
        int mc = kc * CH_;

#pragma unroll
        for (int nt = 0; nt < 16; nt++)
#pragma unroll
            for (int q = 0; q < 4; q++) sacc[nt][q] = 0.0f;

#pragma unroll
        for (int ks = 0; ks < 4; ks++) {
#pragma unroll
            for (int ntp = 0; ntp < 8; ntp++) {
                int g = lane >> 3;
                int row = ntp * 16 + (g >> 1) * 8 + (lane & 7);
                int col = ks * 16 + (g & 1) * 8;
                uint32_t h0, h1, h2, h3, l0, l1, l2, l3;
                ldsm4(h0, h1, h2, h3, kh_b + (uint32_t)(row * KROW_ + col) * 2);
                ldsm4(l0, l1, l2, l3, kl_b + (uint32_t)(row * KROW_ + col) * 2);
                mma2(sacc[2 * ntp], qfh[ks], h0, h1);
                mma2(sacc[2 * ntp], qfh[ks], l0, l1);
                mma2(sacc[2 * ntp], qfl[ks], h0, h1);
                mma2(sacc[2 * ntp + 1], qfh[ks], h2, h3);
                mma2(sacc[2 * ntp + 1], qfh[ks], l2, l3);
                mma2(sacc[2 * ntp + 1], qfl[ks], h2, h3);
            }
        }

        int grow0 = w * 16 + lr;
#pragma unroll
        for (int nt = 0; nt < 16; nt++) {
            unsigned long long ma = (nt < 8) ? a0 : a1;
            unsigned long long mb = (nt < 8) ? b0_ : b1_;
            int bit = (nt & 7) * 8 + lq * 2;
            float e0 = ((ma >> bit) & 1) ? __expf(sacc[nt][0] * 0.125f) * inv0 : 0.0f;
            float e1 = ((ma >> (bit + 1)) & 1) ? __expf(sacc[nt][1] * 0.125f) * inv0 : 0.0f;
            float e2 = ((mb >> bit) & 1) ? __expf(sacc[nt][2] * 0.125f) * inv1 : 0.0f;
            float e3 = ((mb >> (bit + 1)) & 1) ? __expf(sacc[nt][3] * 0.125f) * inv1 : 0.0f;
            int col = mc + nt * 8 + lq * 2;
            *(float2*)(attn_z + (long)grow0 * HW_ + col) = make_float2(e0, e1);
            *(float2*)(attn_z + (long)(grow0 + 8) * HW_ + col) = make_float2(e2, e3);
        }
        __syncthreads();
    }
}

// ---------------- launch ---------------------------------------------------
extern "C" void kernel_launch(void* const* d_in, const int* in_sizes, int n_in,
                              void* d_out, int out_size) {
    const float* query   = (const float*)d_in[0];
    const float* key     = (const float*)d_in[1];
    const float* value   = (const float*)d_in[2];
    const float* x_tilde = (const float*)d_in[3];
    const float* x_hat   = (const float*)d_in[4];
    const float* Wq = (const float*)d_in[5];
    const float* bq = (const float*)d_in[6];
    const float* Wk = (const float*)d_in[7];
    const float* bk = (const float*)d_in[8];
    const float* Wv = (const float*)d_in[9];
    const float* bv = (const float*)d_in[10];
    const float* Wo = (const float*)d_in[11];
    const float* bo = (const float*)d_in[12];

    float* out = (float*)d_out;
    float* attn = out + (size_t)B_ * N_ * D_;

    __nv_bfloat16 *qh, *ql, *kh, *kl, *vh, *vl, *wh, *wl;
    __nv_bfloat16 *Qh, *Ql, *Kh, *Kl, *Vh, *Vl, *ch, *cl;
    unsigned long long* Mb;
    cudaGetSymbolAddress((void**)&qh, g_qh);   cudaGetSymbolAddress((void**)&ql, g_ql);
    cudaGetSymbolAddress((void**)&kh, g_kh);   cudaGetSymbolAddress((void**)&kl, g_kl);
    cudaGetSymbolAddress((void**)&vh, g_vh);   cudaGetSymbolAddress((void**)&vl, g_vl);
    cudaGetSymbolAddress((void**)&wh, g_wh);   cudaGetSymbolAddress((void**)&wl, g_wl);
    cudaGetSymbolAddress((void**)&Qh, g_Qh);   cudaGetSymbolAddress((void**)&Ql, g_Ql);
    cudaGetSymbolAddress((void**)&Kh, g_Kh);   cudaGetSymbolAddress((void**)&Kl, g_Kl);
    cudaGetSymbolAddress((void**)&Vh, g_Vh);   cudaGetSymbolAddress((void**)&Vl, g_Vl);
    cudaGetSymbolAddress((void**)&ch, g_ctxh); cudaGetSymbolAddress((void**)&cl, g_ctxl);
    cudaGetSymbolAddress((void**)&Mb, g_maskb);

    cudaFuncSetAttribute(qkv_proj, cudaFuncAttributeMaxDynamicSharedMemorySize, SMEM_BIG);
    cudaFuncSetAttribute(out_proj, cudaFuncAttributeMaxDynamicSharedMemorySize, SMEM_BIG);
    cudaFuncSetAttribute(fused_attn, cudaFuncAttributeMaxDynamicSharedMemorySize,
                         FUSED_SMEM);

    // launch 0: mask (bit-packed)
    mask_kernel<<<(N_ * HW_ + 255) / 256, 256>>>(x_tilde, x_hat, (unsigned int*)Mb);

    // launch 1: all splits
    split_all<<<(NTOT4 + 255) / 256, 256>>>(
        (const float4*)query, (const float4*)key, (const float4*)value,
        (const float4*)Wq, (const float4*)Wk, (const float4*)Wv, (const float4*)Wo,
        (uint2*)qh, (uint2*)ql, (uint2*)kh, (uint2*)kl, (uint2*)vh, (uint2*)vl,
        (uint2*)wh, (uint2*)wl);

    // launch 2: merged Q/K/V projections
    qkv_proj<<<dim3(4, 288), 256, SMEM_BIG>>>(qh, ql, kh, kl, vh, vl, wh, wl,
                                              bq, bk, bv, Qh, Ql, Kh, Kl, Vh, Vl);

    // launch 3: fused attention (R10 geometry + L2 bitmask)
    fused_attn<<<dim3(N_ / 128, ZTOT), 256, FUSED_SMEM>>>(
        Qh, Ql, Kh, Kl, Vh, Vl, Mb, attn, ch, cl);

    // launch 4: out projection
    out_proj<<<dim3(4, 32), 256, SMEM_BIG>>>(ch, cl, wh, wl, bo, out);
}